// round 11
// baseline (speedup 1.0000x reference)
#include <cuda_runtime.h>

// PowerLinear, single fused kernel with distributed reduction barriers.
//   c = colsum(R), rs = rowsum(R)
//   n_b == 0 : y_b = (c . x_b) * rs     (sum of chunk-local cxp * rs over ks)
//   n_b >= 1 : y_b = R @ ( d^{n_b} * c * x_b )
// Grid 256 = 16 i-tiles x 16 k-chunks; each block contributes its R-tile's
// column/row sums to global accumulators guarded by monotonic counters
// (graph-replay safe: parity double buffers, last-reader zeroing).

#define DD 1024
#define KCHUNK 64
#define PADB 68           // float pad
#define PADW 66           // u64 pad

#define SWD_BYTES (KCHUNK * PADW * 8)       // 33792
#define SB_BYTES  (KCHUNK * PADB * 4)       // 17408
#define OFF_SCRED (SWD_BYTES + SB_BYTES)    // 51200
#define OFF_C     (OFF_SCRED + 1024)        // 52224
#define OFF_RS    (OFF_C + 256)             // 52480
#define OFF_CXP   (OFF_RS + 256)            // 52736
#define OFF_N0    (OFF_CXP + 256)           // 52992
#define OFF_MISC  (OFF_N0 + 256)            // 53248
#define SMEM_TOTAL (OFF_MISC + 64)          // 53312

typedef unsigned long long u64;

__device__ float    g_cs[2][16][64];   // colsum accumulators (parity, ks)
__device__ float    g_rss[2][16][64];  // rowsum accumulators (parity, it)
__device__ unsigned g_ccnt[16];        // produce counters per ks (monotonic)
__device__ unsigned g_rcnt[16];        // produce counters per it
__device__ unsigned g_crd[16];         // read counters per ks
__device__ unsigned g_rrd[16];         // read counters per it

__device__ __forceinline__ void redadd1(float* p, float v)
{
    asm volatile("red.global.add.f32 [%0], %1;" :: "l"(p), "f"(v) : "memory");
}
__device__ __forceinline__ void redadd2(float* p, float a, float b)
{
    asm volatile("red.global.add.v2.f32 [%0], {%1, %2};"
                 :: "l"(p), "f"(a), "f"(b) : "memory");
}
__device__ __forceinline__ u64 pk2(float lo, float hi)
{
    u64 r;
    asm("mov.b64 %0, {%1,%2};" : "=l"(r) : "f"(lo), "f"(hi));
    return r;
}
__device__ __forceinline__ void upk2(u64 v, float& lo, float& hi)
{
    asm("mov.b64 {%0,%1}, %2;" : "=f"(lo), "=f"(hi) : "l"(v));
}
__device__ __forceinline__ void fma2(u64& d, u64 a, u64 b)
{
    asm("fma.rn.f32x2 %0, %1, %2, %0;" : "+l"(d) : "l"(a), "l"(b));
}
__device__ __forceinline__ unsigned ldacq(const unsigned* p)
{
    unsigned v;
    asm volatile("ld.global.acquire.gpu.u32 %0, [%1];" : "=r"(v) : "l"(p));
    return v;
}
__device__ __forceinline__ void spin_until(const unsigned* p, unsigned target)
{
    for (;;) {
        unsigned c = ldacq(p);
        if ((int)(c - target) >= 0) break;
        __nanosleep(32);
    }
}

__global__ __launch_bounds__(256, 2)
void fused_kernel(const float* __restrict__ x,
                  const int*   __restrict__ n,
                  const float* __restrict__ diag,
                  const float* __restrict__ R,
                  float*       __restrict__ out)
{
    extern __shared__ __align__(16) char smem_raw[];
    u64   (*sWd)[PADW]   = (u64 (*)[PADW])(smem_raw);
    float (*sB)[PADB]    = (float (*)[PADB])(smem_raw + SWD_BYTES);
    float (*scred)[64]   = (float (*)[64])(smem_raw + OFF_SCRED);
    float* sm_c   = (float*)(smem_raw + OFF_C);
    float* sm_rs  = (float*)(smem_raw + OFF_RS);
    float* sm_cxp = (float*)(smem_raw + OFF_CXP);
    int*   sm_n0  = (int*)(smem_raw + OFF_N0);
    int*   sm_m   = (int*)(smem_raw + OFF_MISC);   // [0]=pc [1]=pr [2]=cz [3]=rz

    const int bid = blockIdx.x;
    const int tid = threadIdx.x;
    const int it  = bid >> 4;
    const int ks  = bid & 15;
    const int i0  = it * 64;
    const int k0  = ks * KCHUNK;

    // ---- entry: read parities (own contribution pending => count/16 = replay)
    if (tid == 0) {
        unsigned cc = ldacq(&g_ccnt[ks]);
        unsigned rc = ldacq(&g_rcnt[it]);
        sm_m[0] = (int)((cc >> 4) & 1u);
        sm_m[1] = (int)((rc >> 4) & 1u);
    }

    // ---- ks==0 blocks zero their out region (covered by rs barrier below) --
    if (ks == 0) {
        const int b  = tid >> 2;
        const int co = (tid & 3) * 16;
        float4 z = make_float4(0.f, 0.f, 0.f, 0.f);
        float* po = out + b * DD + i0 + co;
        ((float4*)po)[0] = z; ((float4*)po)[1] = z;
        ((float4*)po)[2] = z; ((float4*)po)[3] = z;
    }

    // ---- load R tile --------------------------------------------------------
    const int li = tid >> 2;            // row in tile (i)
    const int lk = (tid & 3) * 4;       // k offset {0,4,8,12}
    const float* rptr = R + (i0 + li) * DD + k0 + lk;
    float4 ra0 = *(const float4*)(rptr);
    float4 ra1 = *(const float4*)(rptr + 16);
    float4 ra2 = *(const float4*)(rptr + 32);
    float4 ra3 = *(const float4*)(rptr + 48);

    // rowsum partial for row li (this thread's 16 values)
    float rsum = (ra0.x + ra0.y + ra0.z + ra0.w) +
                 (ra1.x + ra1.y + ra1.z + ra1.w) +
                 (ra2.x + ra2.y + ra2.z + ra2.w) +
                 (ra3.x + ra3.y + ra3.z + ra3.w);

    // store R tile transposed into sB
    {
        float4 rv[4] = {ra0, ra1, ra2, ra3};
#pragma unroll
        for (int s = 0; s < 4; s++) {
            const int kr = s * 16 + lk;
            sB[kr + 0][li] = rv[s].x;
            sB[kr + 1][li] = rv[s].y;
            sB[kr + 2][li] = rv[s].z;
            sB[kr + 3][li] = rv[s].w;
        }
    }
    __syncthreads();    // publishes sB and parities

    const int pc = sm_m[0];
    const int pr = sm_m[1];

    // rowsum RED (combine 4 threads per row, one RED per row)
    rsum += __shfl_down_sync(0xffffffffu, rsum, 1, 4);
    rsum += __shfl_down_sync(0xffffffffu, rsum, 2, 4);
    if ((tid & 3) == 0) redadd1(&g_rss[pr][it][li], rsum);

    // colsum partial from sB: thread (k = tid&63, seg = tid>>6) sums 16 rows
    {
        const int k   = tid & 63;
        const int seg = tid >> 6;
        const float* row = &sB[k][seg * 16];
        float4 a = ((const float4*)row)[0];
        float4 b = ((const float4*)row)[1];
        float4 c = ((const float4*)row)[2];
        float4 d = ((const float4*)row)[3];
        scred[seg][k] = ((a.x + a.y + a.z + a.w) + (b.x + b.y + b.z + b.w)) +
                        ((c.x + c.y + c.z + c.w) + (d.x + d.y + d.z + d.w));
    }
    __syncthreads();
    if (tid < 64) {
        float cs = (scred[0][tid] + scred[1][tid]) +
                   (scred[2][tid] + scred[3][tid]);
        redadd1(&g_cs[pc][ks][tid], cs);
    }

    // ---- prefetch x/diag for W build (latency overlaps barrier spin) -------
    const int wb = tid >> 2;
    const int wq = (tid & 3) * 4;
    const int nb = n[wb];
    float4 xv[4], dv[4];
#pragma unroll
    for (int m = 0; m < 4; m++) {
        const int kk = wq + 16 * m;
        xv[m] = *(const float4*)(x + wb * DD + k0 + kk);
        dv[m] = *(const float4*)(diag + k0 + kk);
    }

    // ---- publish partials, arrive, spin ------------------------------------
    __threadfence();
    __syncthreads();
    if (tid == 0) {
        unsigned oc = atomicAdd(&g_ccnt[ks], 1u);
        unsigned orr = atomicAdd(&g_rcnt[it], 1u);
        spin_until(&g_ccnt[ks], (oc & ~15u) + 16u);
        spin_until(&g_rcnt[it], (orr & ~15u) + 16u);
    }
    __syncthreads();

    // ---- read final c and rs ----------------------------------------------
    if (tid < 64)        sm_c[tid]       = g_cs[pc][ks][tid];
    else if (tid < 128)  sm_rs[tid - 64] = g_rss[pr][it][tid - 64];
    __syncthreads();

    // read-done; last reader zeroes the parity buffer for its next use
    if (tid == 0) {
        unsigned o1 = atomicAdd(&g_crd[ks], 1u);
        unsigned o2 = atomicAdd(&g_rrd[it], 1u);
        sm_m[2] = ((o1 & 15u) == 15u);
        sm_m[3] = ((o2 & 15u) == 15u);
    }
    __syncthreads();
    if (sm_m[2] && tid < 64)                g_cs[pc][ks][tid] = 0.f;
    if (sm_m[3] && tid >= 64 && tid < 128)  g_rss[pr][it][tid - 64] = 0.f;

    // ---- build duplicated W tile + chunk-local cxp -------------------------
    {
        float cxp = 0.f;
#pragma unroll
        for (int m = 0; m < 4; m++) {
            const int kk = wq + 16 * m;
            float xs[4] = {xv[m].x, xv[m].y, xv[m].z, xv[m].w};
            float ds[4] = {dv[m].x, dv[m].y, dv[m].z, dv[m].w};
#pragma unroll
            for (int c = 0; c < 4; c++) {
                const float cx = sm_c[kk + c] * xs[c];
                cxp += cx;
                float p = 1.f;
#pragma unroll
                for (int k = 0; k < 5; k++) p *= (k < nb) ? ds[c] : 1.f;
                const float w = (nb == 0) ? 0.f : cx * p;
                sWd[kk + c][wb] = pk2(w, w);
            }
        }
        cxp += __shfl_down_sync(0xffffffffu, cxp, 1, 4);
        cxp += __shfl_down_sync(0xffffffffu, cxp, 2, 4);
        if ((tid & 3) == 0) {
            sm_cxp[wb] = cxp;
            sm_n0[wb]  = (nb == 0);
        }
    }
    __syncthreads();

    // ---- main loop: 64 k iterations, 8 FFMA2 each --------------------------
    const int tx = tid & 15;            // i quad
    const int ty = tid >> 4;            // b quad
    const int i4 = tx * 4;
    const int b4 = ty * 4;

    u64 acc[4][2];
#pragma unroll
    for (int r = 0; r < 4; r++) { acc[r][0] = 0ull; acc[r][1] = 0ull; }

#pragma unroll 16
    for (int kk = 0; kk < KCHUNK; kk++) {
        ulonglong2 w01 = *(const ulonglong2*)&sWd[kk][b4];
        ulonglong2 w23 = *(const ulonglong2*)&sWd[kk][b4 + 2];
        ulonglong2 rr  = *(const ulonglong2*)&sB[kk][i4];
        fma2(acc[0][0], w01.x, rr.x); fma2(acc[0][1], w01.x, rr.y);
        fma2(acc[1][0], w01.y, rr.x); fma2(acc[1][1], w01.y, rr.y);
        fma2(acc[2][0], w23.x, rr.x); fma2(acc[2][1], w23.x, rr.y);
        fma2(acc[3][0], w23.y, rr.x); fma2(acc[3][1], w23.y, rr.y);
    }

    // ---- epilogue: vector atomics + n==0 rank-1 term -----------------------
    // (out zeros by the ks==0 sibling are ordered before us by the rs barrier)
    const float rs0 = sm_rs[i4 + 0];
    const float rs1 = sm_rs[i4 + 1];
    const float rs2 = sm_rs[i4 + 2];
    const float rs3 = sm_rs[i4 + 3];
#pragma unroll
    for (int r = 0; r < 4; r++) {
        const int b = b4 + r;
        const float ex = sm_n0[b] ? sm_cxp[b] : 0.f;
        float v0, v1, v2, v3;
        upk2(acc[r][0], v0, v1);
        upk2(acc[r][1], v2, v3);
        float* po = out + b * DD + i0 + i4;
        redadd2(po,     v0 + ex * rs0, v1 + ex * rs1);
        redadd2(po + 2, v2 + ex * rs2, v3 + ex * rs3);
    }
}

// ---------------------------------------------------------------------------
extern "C" void kernel_launch(void* const* d_in, const int* in_sizes, int n_in,
                              void* d_out, int out_size)
{
    const float* x    = (const float*)d_in[0];
    const int*   nn   = (const int*)  d_in[1];
    const float* diag = (const float*)d_in[2];
    const float* rot  = (const float*)d_in[3];
    float* out = (float*)d_out;

    cudaFuncSetAttribute(fused_kernel,
                         cudaFuncAttributeMaxDynamicSharedMemorySize,
                         SMEM_TOTAL);

    fused_kernel<<<256, 256, SMEM_TOTAL>>>(x, nn, diag, rot, out);
}

// round 12
// speedup vs baseline: 1.0146x; 1.0146x over previous
#include <cuda_runtime.h>

// PowerLinear, single fused kernel with distributed reduction barriers.
//   c = colsum(R), rs = rowsum(R)
//   n_b == 0 : y_b = (c . x_b) * rs     (sum of chunk-local cxp * rs over ks)
//   n_b >= 1 : y_b = R @ ( d^{n_b} * c * x_b )
// Grid 256 = 16 i-tiles x 16 k-chunks; each block contributes its R-tile's
// column/row sums to global accumulators guarded by monotonic counters
// (graph-replay safe: parity double buffers, last-reader zeroing).

#define DD 1024
#define KCHUNK 64
#define PADB 68           // float pad
#define PADW 66           // u64 pad

#define SWD_BYTES (KCHUNK * PADW * 8)       // 33792
#define SB_BYTES  (KCHUNK * PADB * 4)       // 17408
#define OFF_SCRED (SWD_BYTES + SB_BYTES)    // 51200
#define OFF_C     (OFF_SCRED + 1024)        // 52224
#define OFF_RS    (OFF_C + 256)             // 52480
#define OFF_CXP   (OFF_RS + 256)            // 52736
#define OFF_N0    (OFF_CXP + 256)           // 52992
#define OFF_MISC  (OFF_N0 + 256)            // 53248
#define SMEM_TOTAL (OFF_MISC + 64)          // 53312

typedef unsigned long long u64;

__device__ float    g_cs[2][16][64];   // colsum accumulators (parity, ks)
__device__ float    g_rss[2][16][64];  // rowsum accumulators (parity, it)
__device__ unsigned g_ccnt[16];        // produce counters per ks (monotonic)
__device__ unsigned g_rcnt[16];        // produce counters per it
__device__ unsigned g_crd[16];         // read counters per ks
__device__ unsigned g_rrd[16];         // read counters per it

__device__ __forceinline__ void redadd1(float* p, float v)
{
    asm volatile("red.global.add.f32 [%0], %1;" :: "l"(p), "f"(v) : "memory");
}
__device__ __forceinline__ void redadd2(float* p, float a, float b)
{
    asm volatile("red.global.add.v2.f32 [%0], {%1, %2};"
                 :: "l"(p), "f"(a), "f"(b) : "memory");
}
__device__ __forceinline__ u64 pk2(float lo, float hi)
{
    u64 r;
    asm("mov.b64 %0, {%1,%2};" : "=l"(r) : "f"(lo), "f"(hi));
    return r;
}
__device__ __forceinline__ void upk2(u64 v, float& lo, float& hi)
{
    asm("mov.b64 {%0,%1}, %2;" : "=f"(lo), "=f"(hi) : "l"(v));
}
__device__ __forceinline__ void fma2(u64& d, u64 a, u64 b)
{
    asm("fma.rn.f32x2 %0, %1, %2, %0;" : "+l"(d) : "l"(a), "l"(b));
}
__device__ __forceinline__ unsigned ldacq(const unsigned* p)
{
    unsigned v;
    asm volatile("ld.global.acquire.gpu.u32 %0, [%1];" : "=r"(v) : "l"(p));
    return v;
}
__device__ __forceinline__ void spin_until(const unsigned* p, unsigned target)
{
    for (;;) {
        unsigned c = ldacq(p);
        if ((int)(c - target) >= 0) break;
        __nanosleep(32);
    }
}

__global__ __launch_bounds__(256, 2)
void fused_kernel(const float* __restrict__ x,
                  const int*   __restrict__ n,
                  const float* __restrict__ diag,
                  const float* __restrict__ R,
                  float*       __restrict__ out)
{
    extern __shared__ __align__(16) char smem_raw[];
    u64   (*sWd)[PADW]   = (u64 (*)[PADW])(smem_raw);
    float (*sB)[PADB]    = (float (*)[PADB])(smem_raw + SWD_BYTES);
    float (*scred)[64]   = (float (*)[64])(smem_raw + OFF_SCRED);
    float* sm_c   = (float*)(smem_raw + OFF_C);
    float* sm_rs  = (float*)(smem_raw + OFF_RS);
    float* sm_cxp = (float*)(smem_raw + OFF_CXP);
    int*   sm_n0  = (int*)(smem_raw + OFF_N0);
    int*   sm_m   = (int*)(smem_raw + OFF_MISC);   // [0]=pc [1]=pr [2]=cz [3]=rz

    const int bid = blockIdx.x;
    const int tid = threadIdx.x;
    const int it  = bid >> 4;
    const int ks  = bid & 15;
    const int i0  = it * 64;
    const int k0  = ks * KCHUNK;

    // ---- entry: read parities (own contribution pending => count/16 = replay)
    if (tid == 0) {
        unsigned cc = ldacq(&g_ccnt[ks]);
        unsigned rc = ldacq(&g_rcnt[it]);
        sm_m[0] = (int)((cc >> 4) & 1u);
        sm_m[1] = (int)((rc >> 4) & 1u);
    }

    // ---- ks==0 blocks zero their out region (covered by rs barrier below) --
    if (ks == 0) {
        const int b  = tid >> 2;
        const int co = (tid & 3) * 16;
        float4 z = make_float4(0.f, 0.f, 0.f, 0.f);
        float* po = out + b * DD + i0 + co;
        ((float4*)po)[0] = z; ((float4*)po)[1] = z;
        ((float4*)po)[2] = z; ((float4*)po)[3] = z;
    }

    // ---- load R tile --------------------------------------------------------
    const int li = tid >> 2;            // row in tile (i)
    const int lk = (tid & 3) * 4;       // k offset {0,4,8,12}
    const float* rptr = R + (i0 + li) * DD + k0 + lk;
    float4 ra0 = *(const float4*)(rptr);
    float4 ra1 = *(const float4*)(rptr + 16);
    float4 ra2 = *(const float4*)(rptr + 32);
    float4 ra3 = *(const float4*)(rptr + 48);

    // rowsum partial for row li (this thread's 16 values)
    float rsum = (ra0.x + ra0.y + ra0.z + ra0.w) +
                 (ra1.x + ra1.y + ra1.z + ra1.w) +
                 (ra2.x + ra2.y + ra2.z + ra2.w) +
                 (ra3.x + ra3.y + ra3.z + ra3.w);

    // store R tile transposed into sB
    {
        float4 rv[4] = {ra0, ra1, ra2, ra3};
#pragma unroll
        for (int s = 0; s < 4; s++) {
            const int kr = s * 16 + lk;
            sB[kr + 0][li] = rv[s].x;
            sB[kr + 1][li] = rv[s].y;
            sB[kr + 2][li] = rv[s].z;
            sB[kr + 3][li] = rv[s].w;
        }
    }
    __syncthreads();    // publishes sB and parities

    const int pc = sm_m[0];
    const int pr = sm_m[1];

    // rowsum RED (combine 4 threads per row, one RED per row)
    rsum += __shfl_down_sync(0xffffffffu, rsum, 1, 4);
    rsum += __shfl_down_sync(0xffffffffu, rsum, 2, 4);
    if ((tid & 3) == 0) redadd1(&g_rss[pr][it][li], rsum);

    // colsum partial from sB: thread (k = tid&63, seg = tid>>6) sums 16 rows
    {
        const int k   = tid & 63;
        const int seg = tid >> 6;
        const float* row = &sB[k][seg * 16];
        float4 a = ((const float4*)row)[0];
        float4 b = ((const float4*)row)[1];
        float4 c = ((const float4*)row)[2];
        float4 d = ((const float4*)row)[3];
        scred[seg][k] = ((a.x + a.y + a.z + a.w) + (b.x + b.y + b.z + b.w)) +
                        ((c.x + c.y + c.z + c.w) + (d.x + d.y + d.z + d.w));
    }
    __syncthreads();
    if (tid < 64) {
        float cs = (scred[0][tid] + scred[1][tid]) +
                   (scred[2][tid] + scred[3][tid]);
        redadd1(&g_cs[pc][ks][tid], cs);
    }

    // ---- prefetch x/diag for W build (latency overlaps barrier spin) -------
    const int wb = tid >> 2;
    const int wq = (tid & 3) * 4;
    const int nb = n[wb];
    float4 xv[4], dv[4];
#pragma unroll
    for (int m = 0; m < 4; m++) {
        const int kk = wq + 16 * m;
        xv[m] = *(const float4*)(x + wb * DD + k0 + kk);
        dv[m] = *(const float4*)(diag + k0 + kk);
    }

    // ---- publish partials, arrive, spin ------------------------------------
    __threadfence();
    __syncthreads();
    if (tid == 0) {
        unsigned oc = atomicAdd(&g_ccnt[ks], 1u);
        unsigned orr = atomicAdd(&g_rcnt[it], 1u);
        spin_until(&g_ccnt[ks], (oc & ~15u) + 16u);
        spin_until(&g_rcnt[it], (orr & ~15u) + 16u);
    }
    __syncthreads();

    // ---- read final c and rs ----------------------------------------------
    if (tid < 64)        sm_c[tid]       = g_cs[pc][ks][tid];
    else if (tid < 128)  sm_rs[tid - 64] = g_rss[pr][it][tid - 64];
    __syncthreads();

    // read-done; last reader zeroes the parity buffer for its next use
    if (tid == 0) {
        unsigned o1 = atomicAdd(&g_crd[ks], 1u);
        unsigned o2 = atomicAdd(&g_rrd[it], 1u);
        sm_m[2] = ((o1 & 15u) == 15u);
        sm_m[3] = ((o2 & 15u) == 15u);
    }
    __syncthreads();
    if (sm_m[2] && tid < 64)                g_cs[pc][ks][tid] = 0.f;
    if (sm_m[3] && tid >= 64 && tid < 128)  g_rss[pr][it][tid - 64] = 0.f;

    // ---- build duplicated W tile + chunk-local cxp -------------------------
    {
        float cxp = 0.f;
#pragma unroll
        for (int m = 0; m < 4; m++) {
            const int kk = wq + 16 * m;
            float xs[4] = {xv[m].x, xv[m].y, xv[m].z, xv[m].w};
            float ds[4] = {dv[m].x, dv[m].y, dv[m].z, dv[m].w};
#pragma unroll
            for (int c = 0; c < 4; c++) {
                const float cx = sm_c[kk + c] * xs[c];
                cxp += cx;
                float p = 1.f;
#pragma unroll
                for (int k = 0; k < 5; k++) p *= (k < nb) ? ds[c] : 1.f;
                const float w = (nb == 0) ? 0.f : cx * p;
                sWd[kk + c][wb] = pk2(w, w);
            }
        }
        cxp += __shfl_down_sync(0xffffffffu, cxp, 1, 4);
        cxp += __shfl_down_sync(0xffffffffu, cxp, 2, 4);
        if ((tid & 3) == 0) {
            sm_cxp[wb] = cxp;
            sm_n0[wb]  = (nb == 0);
        }
    }
    __syncthreads();

    // ---- main loop: 64 k iterations, 8 FFMA2 each --------------------------
    const int tx = tid & 15;            // i quad
    const int ty = tid >> 4;            // b quad
    const int i4 = tx * 4;
    const int b4 = ty * 4;

    u64 acc[4][2];
#pragma unroll
    for (int r = 0; r < 4; r++) { acc[r][0] = 0ull; acc[r][1] = 0ull; }

#pragma unroll 16
    for (int kk = 0; kk < KCHUNK; kk++) {
        ulonglong2 w01 = *(const ulonglong2*)&sWd[kk][b4];
        ulonglong2 w23 = *(const ulonglong2*)&sWd[kk][b4 + 2];
        ulonglong2 rr  = *(const ulonglong2*)&sB[kk][i4];
        fma2(acc[0][0], w01.x, rr.x); fma2(acc[0][1], w01.x, rr.y);
        fma2(acc[1][0], w01.y, rr.x); fma2(acc[1][1], w01.y, rr.y);
        fma2(acc[2][0], w23.x, rr.x); fma2(acc[2][1], w23.x, rr.y);
        fma2(acc[3][0], w23.y, rr.x); fma2(acc[3][1], w23.y, rr.y);
    }

    // ---- epilogue: vector atomics + n==0 rank-1 term -----------------------
    // (out zeros by the ks==0 sibling are ordered before us by the rs barrier)
    const float rs0 = sm_rs[i4 + 0];
    const float rs1 = sm_rs[i4 + 1];
    const float rs2 = sm_rs[i4 + 2];
    const float rs3 = sm_rs[i4 + 3];
#pragma unroll
    for (int r = 0; r < 4; r++) {
        const int b = b4 + r;
        const float ex = sm_n0[b] ? sm_cxp[b] : 0.f;
        float v0, v1, v2, v3;
        upk2(acc[r][0], v0, v1);
        upk2(acc[r][1], v2, v3);
        float* po = out + b * DD + i0 + i4;
        redadd2(po,     v0 + ex * rs0, v1 + ex * rs1);
        redadd2(po + 2, v2 + ex * rs2, v3 + ex * rs3);
    }
}

// ---------------------------------------------------------------------------
extern "C" void kernel_launch(void* const* d_in, const int* in_sizes, int n_in,
                              void* d_out, int out_size)
{
    const float* x    = (const float*)d_in[0];
    const int*   nn   = (const int*)  d_in[1];
    const float* diag = (const float*)d_in[2];
    const float* rot  = (const float*)d_in[3];
    float* out = (float*)d_out;

    cudaFuncSetAttribute(fused_kernel,
                         cudaFuncAttributeMaxDynamicSharedMemorySize,
                         SMEM_TOTAL);

    fused_kernel<<<256, 256, SMEM_TOTAL>>>(x, nn, diag, rot, out);
}